// round 3
// baseline (speedup 1.0000x reference)
#include <cuda_runtime.h>
#include <math.h>

#define NBLK 304          // 2 CTAs per SM on 152-SM GB300, single wave
#define NTHR 256
#define NCOL 256

// Per-block per-column partial sums of squares (304 KB static scratch).
__device__ float g_partials[NBLK * NCOL];
__device__ unsigned int g_count;   // zero at load; last block resets each call

__global__ void __launch_bounds__(NTHR, 2)
colsq_fused_kernel(const float* __restrict__ d, long long n_f4,
                   float* __restrict__ out) {
    const int tid = threadIdx.x;
    const float4* __restrict__ p = (const float4*)d;

    // Stride in floats = gridDim*NTHR*4 = 304*256*4, a multiple of 256,
    // so every thread touches a fixed 4-column group.
    long long idx = (long long)blockIdx.x * NTHR + tid;
    const long long stride = (long long)gridDim.x * NTHR;

    float a0 = 0.f, a1 = 0.f, a2 = 0.f, a3 = 0.f;

    // Unroll x8: 8 independent LDG.128 in flight per thread.
    long long i = idx;
    for (; i + 7 * stride < n_f4; i += 8 * stride) {
        float4 v0 = p[i];
        float4 v1 = p[i + stride];
        float4 v2 = p[i + 2 * stride];
        float4 v3 = p[i + 3 * stride];
        float4 v4 = p[i + 4 * stride];
        float4 v5 = p[i + 5 * stride];
        float4 v6 = p[i + 6 * stride];
        float4 v7 = p[i + 7 * stride];
        a0 += v0.x * v0.x; a1 += v0.y * v0.y; a2 += v0.z * v0.z; a3 += v0.w * v0.w;
        a0 += v1.x * v1.x; a1 += v1.y * v1.y; a2 += v1.z * v1.z; a3 += v1.w * v1.w;
        a0 += v2.x * v2.x; a1 += v2.y * v2.y; a2 += v2.z * v2.z; a3 += v2.w * v2.w;
        a0 += v3.x * v3.x; a1 += v3.y * v3.y; a2 += v3.z * v3.z; a3 += v3.w * v3.w;
        a0 += v4.x * v4.x; a1 += v4.y * v4.y; a2 += v4.z * v4.z; a3 += v4.w * v4.w;
        a0 += v5.x * v5.x; a1 += v5.y * v5.y; a2 += v5.z * v5.z; a3 += v5.w * v5.w;
        a0 += v6.x * v6.x; a1 += v6.y * v6.y; a2 += v6.z * v6.z; a3 += v6.w * v6.w;
        a0 += v7.x * v7.x; a1 += v7.y * v7.y; a2 += v7.z * v7.z; a3 += v7.w * v7.w;
    }
    for (; i < n_f4; i += stride) {
        float4 v = p[i];
        a0 += v.x * v.x; a1 += v.y * v.y; a2 += v.z * v.z; a3 += v.w * v.w;
    }

    // Deterministic block reduction: 4 replicas of the 256-column vector.
    __shared__ float s[4][NCOL];
    const int c = (tid * 4) & (NCOL - 1);
    const int rep = tid >> 6;  // 0..3
    s[rep][c + 0] = a0;
    s[rep][c + 1] = a1;
    s[rep][c + 2] = a2;
    s[rep][c + 3] = a3;
    __syncthreads();

    float part = s[0][tid] + s[1][tid] + s[2][tid] + s[3][tid];
    g_partials[blockIdx.x * NCOL + tid] = part;

    // --- last-block-done reduction (threadFenceReduction pattern) ---
    __shared__ bool isLast;
    __threadfence();                       // make partial visible before count
    if (tid == 0) {
        unsigned int old = atomicAdd(&g_count, 1u);
        isLast = (old == (unsigned)(gridDim.x - 1));
    }
    __syncthreads();
    if (!isLast) return;

    __threadfence();                       // acquire side

    // Thread tid owns column tid: sum all NBLK partials (coalesced, L2-hot).
    // __ldcg bypasses L1 so we read the freshly written L2 data.
    float s0 = 0.f, s1 = 0.f, s2 = 0.f, s3 = 0.f;
    const float* __restrict__ gp = g_partials;
    int b = 0;
    for (; b + 3 < NBLK; b += 4) {
        s0 += __ldcg(&gp[(b    ) * NCOL + tid]);
        s1 += __ldcg(&gp[(b + 1) * NCOL + tid]);
        s2 += __ldcg(&gp[(b + 2) * NCOL + tid]);
        s3 += __ldcg(&gp[(b + 3) * NCOL + tid]);
    }
    for (; b < NBLK; b++)
        s0 += __ldcg(&gp[b * NCOL + tid]);
    float colsum = (s0 + s1) + (s2 + s3);

    float diff = colsum - 1.0f;
    __shared__ float red[NCOL];
    red[tid] = diff * diff;
    __syncthreads();

    #pragma unroll
    for (int off = NCOL / 2; off >= 32; off >>= 1) {
        if (tid < off) red[tid] += red[tid + off];
        __syncthreads();
    }
    if (tid < 32) {
        float v = red[tid];
        #pragma unroll
        for (int off = 16; off > 0; off >>= 1)
            v += __shfl_down_sync(0xFFFFFFFF, v, off);
        if (tid == 0) {
            out[0] = 0.001f * sqrtf(v);
            g_count = 0;                   // reset for next graph replay
        }
    }
}

extern "C" void kernel_launch(void* const* d_in, const int* in_sizes, int n_in,
                              void* d_out, int out_size) {
    const float* d = (const float*)d_in[0];
    float* out = (float*)d_out;
    long long n = (long long)in_sizes[0];      // 262144 * 256
    long long n_f4 = n / 4;

    colsq_fused_kernel<<<NBLK, NTHR>>>(d, n_f4, out);
}